// round 12
// baseline (speedup 1.0000x reference)
#include <cuda_runtime.h>
#include <cstdint>

// Problem dims
#define B_  16
#define T_  512
#define E_  4096
#define H_  8
#define HD_ 512
#define NBH 128            // B_*H_
#define QSZ 33554432       // B_*T_*E_

// cp.async GEMM tiling (128x64 CTA tile, warp tile 32x32, 3 CTAs/SM)
#define BM 128
#define BN2 64
#define BK 32
#define AST 36    // A smem row stride: frag bank = 4g+t (bijective)
#define BST2 72   // B smem row stride: 72%32==8 -> frag bank = 8t+g (bijective)
#define ASZ (BM * AST)                  // 4608 floats
#define BSZ2 (BK * BST2)                // 2304 floats
#define STG2 (ASZ + BSZ2)               // 6912 floats per stage
#define SMEM2 (2 * STG2 * 4)            // 55296 bytes (2-stage)

// k_scores path (proven 128x128 register-staged)
#define BN 128
#define BST 136
#define BSZ (BK * BST)
#define SMEM_DB ((2 * ASZ + 2 * BSZ) * 4)

// k_qkv L2 grouping: 32 n-tiles (64 cols each) = 32MB weight panel per group
#define GN 32
#define QKV_NT 192         // 12288/64
#define QKV_MT 64          // 8192/128

// Scratch
__device__ float gQ[QSZ];
__device__ float gK[QSZ];
__device__ float gV[QSZ];
__device__ float gS[QSZ];   // scores / probabilities [B,H,T,T]
__device__ float gY[QSZ];   // concat attention output [B,T,E]

// ---------------------------------------------------------------------------
__device__ __forceinline__ uint32_t f2tf(float f) {
    uint32_t u;
    asm("cvt.rna.tf32.f32 %0, %1;" : "=r"(u) : "f"(f));
    return u;
}

__device__ __forceinline__ void mma8(float* c, const uint32_t* a, const uint32_t* b) {
    asm volatile(
        "mma.sync.aligned.m16n8k8.row.col.f32.tf32.tf32.f32 "
        "{%0,%1,%2,%3},{%4,%5,%6,%7},{%8,%9},{%0,%1,%2,%3};\n"
        : "+f"(c[0]), "+f"(c[1]), "+f"(c[2]), "+f"(c[3])
        : "r"(a[0]), "r"(a[1]), "r"(a[2]), "r"(a[3]), "r"(b[0]), "r"(b[1]));
}

__device__ __forceinline__ uint32_t smem_u32(const void* p) {
    uint32_t a;
    asm("{ .reg .u64 t; cvta.to.shared.u64 t, %1; cvt.u32.u64 %0, t; }" : "=r"(a) : "l"(p));
    return a;
}

__device__ __forceinline__ void cpa16(uint32_t s, const void* g) {
    asm volatile("cp.async.cg.shared.global [%0], [%1], 16;" :: "r"(s), "l"(g));
}
#define CPCOMMIT() asm volatile("cp.async.commit_group;" ::: "memory")
#define CPWAIT(n)  asm volatile("cp.async.wait_group %0;" :: "n"(n) : "memory")

// ===========================================================================
// cp.async core: 128x64 CTA tile, 2-stage, warp tile 32x32 (acc[2][4][4])
// SMEM holds raw fp32; tf32 rounding at fragment consume (numerics identical
// to converting at store time).
// ===========================================================================
__device__ __forceinline__ void cp_tile2(uint32_t Aa, uint32_t Ba,
                                         const float* __restrict__ Ag, int lda,
                                         const float* __restrict__ Bg, int ldb,
                                         int kt, int tid) {
    const float* A = Ag + kt * BK;
    const float* B = Bg + (size_t)kt * BK * ldb;
#pragma unroll
    for (int t = 0; t < 4; t++) {                // A: 128 rows x 8 float4
        int idx = t * 256 + tid;
        int r = idx >> 3, kq = idx & 7;
        cpa16(Aa + (uint32_t)(r * AST + kq * 4) * 4,
              A + (size_t)r * lda + kq * 4);
    }
#pragma unroll
    for (int t = 0; t < 2; t++) {                // B: 32 rows x 16 float4
        int idx = t * 256 + tid;
        int k = idx >> 4, nq = idx & 15;
        cpa16(Ba + (uint32_t)(k * BST2 + nq * 4) * 4,
              B + (size_t)k * ldb + nq * 4);
    }
}

__device__ __forceinline__ void zero_acc2(float (&acc)[2][4][4]) {
#pragma unroll
    for (int i = 0; i < 2; i++)
#pragma unroll
        for (int j = 0; j < 4; j++)
#pragma unroll
            for (int k = 0; k < 4; k++) acc[i][j][k] = 0.f;
}

__device__ __forceinline__ void compute2(const float* As, const float* Bs,
                                         float (&acc)[2][4][4],
                                         int lane, int wm, int wn) {
    int g = lane >> 2, t = lane & 3;
#pragma unroll
    for (int s = 0; s < 4; s++) {
        uint32_t a[2][4];
        uint32_t b[4][2];
#pragma unroll
        for (int i = 0; i < 2; i++) {
            const float* ap = As + ((wm * 2 + i) * 16 + g) * AST + s * 8 + t;
            a[i][0] = f2tf(ap[0]);
            a[i][1] = f2tf(ap[8 * AST]);
            a[i][2] = f2tf(ap[4]);
            a[i][3] = f2tf(ap[8 * AST + 4]);
        }
#pragma unroll
        for (int j = 0; j < 4; j++) {
            const float* bp = Bs + (s * 8 + t) * BST2 + (wn * 4 + j) * 8 + g;
            b[j][0] = f2tf(bp[0]);
            b[j][1] = f2tf(bp[4 * BST2]);
        }
#pragma unroll
        for (int i = 0; i < 2; i++)
#pragma unroll
            for (int j = 0; j < 4; j++)
                mma8(acc[i][j], a[i], b[j]);
    }
}

// Hazard: cp issued at iter kt fills stage (kt+1)&1, last computed at kt-1;
// the trailing __syncthreads of iter kt-1 orders that compute before this fill.
__device__ __forceinline__ void gemm2(const float* __restrict__ Ag, int lda,
                                      const float* __restrict__ Bg, int ldb,
                                      int nkt, float* sm, uint32_t sb,
                                      float (&acc)[2][4][4],
                                      int tid, int lane, int wm, int wn) {
    cp_tile2(sb, sb + ASZ * 4, Ag, lda, Bg, ldb, 0, tid);
    CPCOMMIT();
    for (int kt = 0; kt < nkt; kt++) {
        int cs = kt & 1;
        if (kt + 1 < nkt) {
            int ns = cs ^ 1;
            cp_tile2(sb + (uint32_t)(ns * STG2) * 4,
                     sb + (uint32_t)(ns * STG2 + ASZ) * 4,
                     Ag, lda, Bg, ldb, kt + 1, tid);
            CPCOMMIT();
            CPWAIT(1);
        } else {
            CPWAIT(0);
        }
        __syncthreads();
        compute2(sm + cs * STG2, sm + cs * STG2 + ASZ, acc, lane, wm, wn);
        if (kt + 1 < nkt) __syncthreads();
    }
}

__device__ __forceinline__ void store_acc2(float* C, int ldc,
                                           const float (&acc)[2][4][4],
                                           int lane, int wm, int wn) {
    int g = lane >> 2, t = lane & 3;
#pragma unroll
    for (int i = 0; i < 2; i++)
#pragma unroll
        for (int j = 0; j < 4; j++) {
            int r0 = (wm * 2 + i) * 16 + g;
            int c0 = (wn * 4 + j) * 8 + t * 2;
            float* p = C + (size_t)r0 * ldc + c0;
            p[0] = acc[i][j][0];
            p[1] = acc[i][j][1];
            p[(size_t)8 * ldc]     = acc[i][j][2];
            p[(size_t)8 * ldc + 1] = acc[i][j][3];
        }
}

// ---------------------------------------------------------------------------
// Kernel 1: fused QKV projection, group-major 1D grid (L2-resident W panels)
// ---------------------------------------------------------------------------
__global__ __launch_bounds__(256, 3) void k_qkv(const float* __restrict__ data,
                                                const float* __restrict__ Wq,
                                                const float* __restrict__ Wk,
                                                const float* __restrict__ Wv) {
    extern __shared__ __align__(16) float smf[];
    uint32_t sb = smem_u32(smf);
    int tid = threadIdx.x, lane = tid & 31, wid = tid >> 5;
    int wm = wid >> 1, wn = wid & 1;

    int gid = blockIdx.x;
    int grp = gid / (GN * QKV_MT);
    int rem = gid % (GN * QKV_MT);
    int m0 = (rem / GN) * BM;
    int n0 = (grp * GN + (rem % GN)) * BN2;

    int which = n0 >> 12;          // 0:q 1:k 2:v
    int nr = n0 & 4095;
    int h = nr >> 9, d0 = nr & 511;
    const float* W = (which == 0) ? Wq : (which == 1) ? Wk : Wv;
    const float* Bg = W + (size_t)h * E_ * HD_ + d0;      // ldb = HD_
    const float* Ag = data + (size_t)m0 * E_;

    float acc[2][4][4];
    zero_acc2(acc);
    gemm2(Ag, E_, Bg, HD_, E_ / BK, smf, sb, acc, tid, lane, wm, wn);

    float* ob = (which == 0) ? gQ : (which == 1) ? gK : gV;
    int b = m0 >> 9, t0 = m0 & 511;
    float* C = ob + ((size_t)(b * H_ + h) * T_ + t0) * HD_ + d0;
    store_acc2(C, HD_, acc, lane, wm, wn);
}

// ---------------------------------------------------------------------------
// Kernel 4: O = P V (causal-truncated K loop) -> gY concat layout
// ---------------------------------------------------------------------------
__global__ __launch_bounds__(256, 3) void k_av() {
    extern __shared__ __align__(16) float smf[];
    uint32_t sb = smem_u32(smf);
    int tid = threadIdx.x, lane = tid & 31, wid = tid >> 5;
    int wm = wid >> 1, wn = wid & 1;

    int n0 = blockIdx.x * BN2;     // d0
    int m0 = blockIdx.y * BM;      // t0
    int z = blockIdx.z;
    int b = z >> 3, h = z & 7;

    const float* Ag = gS + (size_t)z * T_ * T_ + (size_t)m0 * T_;
    const float* Bg = gV + (size_t)z * T_ * HD_ + n0;
    int nkt = (m0 + BM) / BK;      // causal truncation

    float acc[2][4][4];
    zero_acc2(acc);
    gemm2(Ag, T_, Bg, HD_, nkt, smf, sb, acc, tid, lane, wm, wn);

    float* C = gY + ((size_t)b * T_ + m0) * E_ + h * HD_ + n0;
    store_acc2(C, E_, acc, lane, wm, wn);
}

// ---------------------------------------------------------------------------
// Kernel 5: out = Y @ Wo + bo (Wo 64MB: L2-resident under x-major waves)
// ---------------------------------------------------------------------------
__global__ __launch_bounds__(256, 3) void k_out(const float* __restrict__ Wo,
                                                const float* __restrict__ bo,
                                                float* __restrict__ out) {
    extern __shared__ __align__(16) float smf[];
    uint32_t sb = smem_u32(smf);
    int tid = threadIdx.x, lane = tid & 31, wid = tid >> 5;
    int wm = wid >> 1, wn = wid & 1;

    int n0 = blockIdx.x * BN2;
    int m0 = blockIdx.y * BM;

    const float* Ag = gY + (size_t)m0 * E_;
    const float* Bg = Wo + n0;

    float acc[2][4][4];
    zero_acc2(acc);
    gemm2(Ag, E_, Bg, E_, E_ / BK, smf, sb, acc, tid, lane, wm, wn);

    float* C = out + (size_t)m0 * E_ + n0;
    int g = lane >> 2, t = lane & 3;
#pragma unroll
    for (int i = 0; i < 2; i++)
#pragma unroll
        for (int j = 0; j < 4; j++) {
            int r0 = (wm * 2 + i) * 16 + g;
            int c0 = (wn * 4 + j) * 8 + t * 2;
            float b0 = bo[n0 + c0], b1 = bo[n0 + c0 + 1];
            float* p = C + (size_t)r0 * E_ + c0;
            p[0]           = acc[i][j][0] + b0;
            p[1]           = acc[i][j][1] + b1;
            p[8 * E_]      = acc[i][j][2] + b0;
            p[8 * E_ + 1]  = acc[i][j][3] + b1;
        }
}

// ===========================================================================
// k_scores: proven 128x128 register-staged double-buffered path (transposed B)
// ===========================================================================
__device__ __forceinline__ void ldgA(const float* __restrict__ Ag, int lda,
                                     float4* v, int tid) {
#pragma unroll
    for (int t = 0; t < 4; t++) {
        int idx = t * 256 + tid;
        int row = idx >> 3, kq = idx & 7;
        v[t] = *reinterpret_cast<const float4*>(Ag + (size_t)row * lda + kq * 4);
    }
}
__device__ __forceinline__ void ldgBt(const float* __restrict__ Bg, int ldb,
                                      float4* v, int tid) {
#pragma unroll
    for (int t = 0; t < 4; t++) {
        int idx = t * 256 + tid;
        int n = idx >> 3, kq = idx & 7;
        v[t] = *reinterpret_cast<const float4*>(Bg + (size_t)n * ldb + kq * 4);
    }
}
__device__ __forceinline__ void stsA(uint32_t* As, const float4* v, int tid) {
#pragma unroll
    for (int t = 0; t < 4; t++) {
        int idx = t * 256 + tid;
        int row = idx >> 3, kq = idx & 7;
        uint4 u;
        u.x = f2tf(v[t].x); u.y = f2tf(v[t].y); u.z = f2tf(v[t].z); u.w = f2tf(v[t].w);
        *reinterpret_cast<uint4*>(As + row * AST + kq * 4) = u;
    }
}
__device__ __forceinline__ void stsBt(uint32_t* Bs, const float4* v, int tid) {
#pragma unroll
    for (int t = 0; t < 4; t++) {
        int idx = t * 256 + tid;
        int n = idx >> 3, kq = idx & 7;
        int k = kq * 4;
        Bs[(k + 0) * BST + n] = f2tf(v[t].x);
        Bs[(k + 1) * BST + n] = f2tf(v[t].y);
        Bs[(k + 2) * BST + n] = f2tf(v[t].z);
        Bs[(k + 3) * BST + n] = f2tf(v[t].w);
    }
}
__device__ __forceinline__ void compute_tile(const uint32_t* As, const uint32_t* Bs,
                                             float (&acc)[4][4][4],
                                             int lane, int wm, int wn) {
    int g = lane >> 2, t = lane & 3;
#pragma unroll
    for (int s = 0; s < 4; s++) {
        uint32_t a[4][4];
        uint32_t b[4][2];
#pragma unroll
        for (int i = 0; i < 4; i++) {
            const uint32_t* ap = As + ((wm * 4 + i) * 16 + g) * AST + s * 8 + t;
            a[i][0] = ap[0];
            a[i][1] = ap[8 * AST];
            a[i][2] = ap[4];
            a[i][3] = ap[8 * AST + 4];
        }
#pragma unroll
        for (int j = 0; j < 4; j++) {
            const uint32_t* bp = Bs + (s * 8 + t) * BST + (wn * 4 + j) * 8 + g;
            b[j][0] = bp[0];
            b[j][1] = bp[4 * BST];
        }
#pragma unroll
        for (int i = 0; i < 4; i++)
#pragma unroll
            for (int j = 0; j < 4; j++)
                mma8(acc[i][j], a[i], b[j]);
    }
}

__global__ __launch_bounds__(256) void k_scores() {
    int n0 = blockIdx.x * BN;
    int m0 = blockIdx.y * BM;
    if (n0 > m0) return;                         // fully masked tile
    int z = blockIdx.z;

    extern __shared__ __align__(16) float smf[];
    uint32_t* As = reinterpret_cast<uint32_t*>(smf);
    uint32_t* Bs = As + 2 * ASZ;
    int tid = threadIdx.x, lane = tid & 31, wid = tid >> 5;
    int wm = wid >> 2, wn = wid & 3;

    const float* Ag = gQ + (size_t)z * T_ * HD_ + (size_t)m0 * HD_;
    const float* Bg = gK + (size_t)z * T_ * HD_ + (size_t)n0 * HD_;

    float acc[4][4][4];
#pragma unroll
    for (int i = 0; i < 4; i++)
#pragma unroll
        for (int j = 0; j < 4; j++)
#pragma unroll
            for (int k = 0; k < 4; k++) acc[i][j][k] = 0.f;

    float4 av[4], bv[4];
    ldgA(Ag, HD_, av, tid);
    ldgBt(Bg, HD_, bv, tid);
    stsA(As, av, tid);
    stsBt(Bs, bv, tid);
    __syncthreads();
    const int nkt = HD_ / BK;
    for (int kt = 0; kt < nkt; kt++) {
        int cb = kt & 1, nb = cb ^ 1;
        bool more = (kt + 1 < nkt);
        if (more) {
            ldgA(Ag + (kt + 1) * BK, HD_, av, tid);
            ldgBt(Bg + (kt + 1) * BK, HD_, bv, tid);
        }
        compute_tile(As + cb * ASZ, Bs + cb * BSZ, acc, lane, wm, wn);
        if (more) {
            stsA(As + nb * ASZ, av, tid);
            stsBt(Bs + nb * BSZ, bv, tid);
            __syncthreads();
        }
    }

    const float sc = 0.015625f;                  // 1/sqrt(4096)
    float* C = gS + (size_t)z * T_ * T_ + (size_t)m0 * T_ + n0;
    int g = lane >> 2, t = lane & 3;
#pragma unroll
    for (int i = 0; i < 4; i++)
#pragma unroll
        for (int j = 0; j < 4; j++) {
            int r0 = (wm * 4 + i) * 16 + g;
            int c0 = (wn * 4 + j) * 8 + t * 2;
            int gr = m0 + r0, gc = n0 + c0;
            float* p = C + (size_t)r0 * T_ + c0;
            if (gc     <= gr)     p[0]          = acc[i][j][0] * sc;
            if (gc + 1 <= gr)     p[1]          = acc[i][j][1] * sc;
            if (gc     <= gr + 8) p[8 * T_]     = acc[i][j][2] * sc;
            if (gc + 1 <= gr + 8) p[8 * T_ + 1] = acc[i][j][3] * sc;
        }
}

// ---------------------------------------------------------------------------
// Kernel 3: causal row softmax; zero-fills masked tail (lets PV over-read)
// ---------------------------------------------------------------------------
__global__ __launch_bounds__(128) void k_softmax() {
    int r = blockIdx.x;
    int z = blockIdx.y;
    float* row = gS + (size_t)z * T_ * T_ + (size_t)r * T_;
    int n = r + 1;
    int tid = threadIdx.x;
    __shared__ float sm[4];

    float v = -3.4e38f;
    for (int i = tid; i < n; i += 128) v = fmaxf(v, row[i]);
#pragma unroll
    for (int o = 16; o; o >>= 1) v = fmaxf(v, __shfl_xor_sync(0xffffffffu, v, o));
    if ((tid & 31) == 0) sm[tid >> 5] = v;
    __syncthreads();
    float M = fmaxf(fmaxf(sm[0], sm[1]), fmaxf(sm[2], sm[3]));
    __syncthreads();

    float s = 0.f;
    for (int i = tid; i < n; i += 128) {
        float e = __expf(row[i] - M);
        row[i] = e;
        s += e;
    }
#pragma unroll
    for (int o = 16; o; o >>= 1) s += __shfl_xor_sync(0xffffffffu, s, o);
    if ((tid & 31) == 0) sm[tid >> 5] = s;
    __syncthreads();
    float inv = 1.f / (sm[0] + sm[1] + sm[2] + sm[3]);

    for (int i = tid; i < T_; i += 128)
        row[i] = (i < n) ? row[i] * inv : 0.f;
}

// ---------------------------------------------------------------------------
extern "C" void kernel_launch(void* const* d_in, const int* in_sizes, int n_in,
                              void* d_out, int out_size) {
    const float* data = (const float*)d_in[0];
    const float* Wq   = (const float*)d_in[1];
    const float* Wk   = (const float*)d_in[2];
    const float* Wv   = (const float*)d_in[3];
    const float* Wo   = (const float*)d_in[4];
    const float* bo   = (const float*)d_in[5];
    float* out = (float*)d_out;

    static int attr_done = 0;
    if (!attr_done) {
        cudaFuncSetAttribute(k_qkv,    cudaFuncAttributeMaxDynamicSharedMemorySize, SMEM2);
        cudaFuncSetAttribute(k_av,     cudaFuncAttributeMaxDynamicSharedMemorySize, SMEM2);
        cudaFuncSetAttribute(k_out,    cudaFuncAttributeMaxDynamicSharedMemorySize, SMEM2);
        cudaFuncSetAttribute(k_scores, cudaFuncAttributeMaxDynamicSharedMemorySize, SMEM_DB);
        attr_done = 1;
    }

    k_qkv   <<<QKV_NT * QKV_MT,  256, SMEM2>>>(data, Wq, Wk, Wv);
    k_scores<<<dim3(4, 4, NBH),  256, SMEM_DB>>>();
    k_softmax<<<dim3(T_, NBH),   128>>>();
    k_av    <<<dim3(8, 4, NBH),  256, SMEM2>>>();
    k_out   <<<dim3(64, 64),     256, SMEM2>>>(Wo, bo, out);
}

// round 14
// speedup vs baseline: 2.3987x; 2.3987x over previous
#include <cuda_runtime.h>
#include <cuda_fp16.h>
#include <cstdint>

// Problem dims
#define B_  16
#define T_  512
#define E_  4096
#define H_  8
#define HD_ 512
#define NBH 128            // B_*H_
#define QSZ 33554432       // B_*T_*E_

// fp16 GEMM tiling: CTA 128x128, BK=32 halves (16 u32 k-pairs), warp 64x32
#define BM 128
#define BN 128
#define BK 32
#define ASTH 20            // A smem row stride (u32): bank 4g+t bijective
#define BSTH 136           // interleaved-B stride (u32): bank 8t+g bijective
#define KSTH 20            // scores-B (n-row) stride (u32)
#define ASZH (BM * ASTH)   // 2560 u32
#define BSZH (16 * BSTH)   // 2176 u32
#define KSZH (BM * KSTH)   // 2560 u32
#define SMEM_I (3 * (ASZH + BSZH) * 4)   // 56832 B
#define SMEM_S (3 * (ASZH + KSZH) * 4)   // 61440 B

// k_qkv L2 grouping (proven R9): 16 n-tiles/group
#define GN 16
#define QKV_NT 96
#define QKV_MT 64

// ---------------------------------------------------------------------------
// Scratch (device globals)
// ---------------------------------------------------------------------------
__device__ __align__(128) __half   hD[QSZ];                    // data fp16 [8192][4096]
__device__ __align__(128) uint32_t hW2[3u * 8u * 2048u * 512u];// Wq|Wk|Wv k-pair interleaved
__device__ __align__(128) uint32_t hWo2[2048u * 4096u];        // Wo interleaved
__device__ __align__(128) __half   gQh[QSZ];                   // Q fp16 [bh][t][d]
__device__ __align__(128) __half   gKh[QSZ];                   // K fp16 [bh][s][d]
__device__ __align__(128) __half   gVh[QSZ];                   // V fp16 interleaved [bh][s/2][d][2]
__device__ float  gS[QSZ];                                     // scores fp32 [bh][t][s]
__device__ __align__(128) __half   gPh[QSZ];                   // probs fp16 [bh][t][s]
__device__ __align__(128) __half   gYh[QSZ];                   // attn out fp16 [b*T+t][E]

// ---------------------------------------------------------------------------
__device__ __forceinline__ uint32_t smem_u32(const void* p) {
    uint32_t a;
    asm("{ .reg .u64 t; cvta.to.shared.u64 t, %1; cvt.u32.u64 %0, t; }" : "=r"(a) : "l"(p));
    return a;
}
__device__ __forceinline__ void cpa16(uint32_t s, const void* g) {
    asm volatile("cp.async.cg.shared.global [%0], [%1], 16;" :: "r"(s), "l"(g));
}
#define CPCOMMIT() asm volatile("cp.async.commit_group;" ::: "memory")
#define CPWAIT(n)  asm volatile("cp.async.wait_group %0;" :: "n"(n) : "memory")

__device__ __forceinline__ void mma16(float* c, const uint32_t* a, const uint32_t* b) {
    asm volatile(
        "mma.sync.aligned.m16n8k16.row.col.f32.f16.f16.f32 "
        "{%0,%1,%2,%3},{%4,%5,%6,%7},{%8,%9},{%0,%1,%2,%3};\n"
        : "+f"(c[0]), "+f"(c[1]), "+f"(c[2]), "+f"(c[3])
        : "r"(a[0]), "r"(a[1]), "r"(a[2]), "r"(a[3]), "r"(b[0]), "r"(b[1]));
}

__device__ __forceinline__ void zero_acc(float (&acc)[4][4][4]) {
#pragma unroll
    for (int i = 0; i < 4; i++)
#pragma unroll
        for (int j = 0; j < 4; j++)
#pragma unroll
            for (int k = 0; k < 4; k++) acc[i][j][k] = 0.f;
}

// ===========================================================================
// fp16 cp.async GEMM core, 3-stage
// A: fp16 row-major [row][k]; B mode0: u32 interleaved [kp][n]; mode1: fp16 n-rows [n][k]
// ===========================================================================
__device__ __forceinline__ void cp_tileA(uint32_t Aa, const __half* __restrict__ Ah,
                                         int lda, int kt, int tid) {
#pragma unroll
    for (int t = 0; t < 2; t++) {
        int idx = t * 256 + tid;
        int r = idx >> 2, kq = idx & 3;
        cpa16(Aa + (uint32_t)(r * ASTH + kq * 4) * 4,
              Ah + (size_t)r * lda + kt * 32 + kq * 8);
    }
}
__device__ __forceinline__ void cp_tileB0(uint32_t Ba, const uint32_t* __restrict__ B2,
                                          int ldb2, int kt, int tid) {
#pragma unroll
    for (int t = 0; t < 2; t++) {
        int idx = t * 256 + tid;
        int kp = idx >> 5, nq = idx & 31;
        cpa16(Ba + (uint32_t)(kp * BSTH + nq * 4) * 4,
              B2 + (size_t)(kt * 16 + kp) * ldb2 + nq * 4);
    }
}
__device__ __forceinline__ void cp_tileB1(uint32_t Ba, const __half* __restrict__ Bh,
                                          int ldb, int kt, int tid) {
#pragma unroll
    for (int t = 0; t < 2; t++) {
        int idx = t * 256 + tid;
        int r = idx >> 2, kq = idx & 3;
        cpa16(Ba + (uint32_t)(r * KSTH + kq * 4) * 4,
              Bh + (size_t)r * ldb + kt * 32 + kq * 8);
    }
}

template <int BMODE>
__device__ __forceinline__ void compute_h(const uint32_t* As, const uint32_t* Bs,
                                          float (&acc)[4][4][4],
                                          int lane, int wm, int wn) {
    int g = lane >> 2, t = lane & 3;
#pragma unroll
    for (int s = 0; s < 2; s++) {                // two k16 steps per BK=32
        uint32_t a[4][4];
        uint32_t b[4][2];
#pragma unroll
        for (int i = 0; i < 4; i++) {
            const uint32_t* ap = As + ((wm * 4 + i) * 16 + g) * ASTH + s * 8 + t;
            a[i][0] = ap[0];
            a[i][1] = ap[8 * ASTH];
            a[i][2] = ap[4];
            a[i][3] = ap[8 * ASTH + 4];
        }
#pragma unroll
        for (int j = 0; j < 4; j++) {
            if (BMODE == 0) {
                const uint32_t* bp = Bs + (s * 8 + t) * BSTH + (wn * 4 + j) * 8 + g;
                b[j][0] = bp[0];
                b[j][1] = bp[4 * BSTH];
            } else {
                const uint32_t* bp = Bs + ((wn * 4 + j) * 8 + g) * KSTH + s * 8 + t;
                b[j][0] = bp[0];
                b[j][1] = bp[4];
            }
        }
#pragma unroll
        for (int i = 0; i < 4; i++)
#pragma unroll
            for (int j = 0; j < 4; j++)
                mma16(acc[i][j], a[i], b[j]);
    }
}

// 3-stage driver; hazard discipline identical to the proven R9 loop.
template <int BMODE>
__device__ __forceinline__ void gemm_h(const __half* __restrict__ Ag, int lda,
                                       const void* __restrict__ Bgv, int ldb,
                                       int nkt, const uint32_t* sm, uint32_t sb,
                                       float (&acc)[4][4][4],
                                       int tid, int lane, int wm, int wn) {
    const int BSZT = (BMODE ? KSZH : BSZH);
    const int STGT = ASZH + BSZT;

    cp_tileA(sb, Ag, lda, 0, tid);
    if (BMODE == 0) cp_tileB0(sb + ASZH * 4, (const uint32_t*)Bgv, ldb, 0, tid);
    else            cp_tileB1(sb + ASZH * 4, (const __half*)Bgv, ldb, 0, tid);
    CPCOMMIT();
    if (nkt > 1) {
        uint32_t b1 = sb + (uint32_t)STGT * 4;
        cp_tileA(b1, Ag, lda, 1, tid);
        if (BMODE == 0) cp_tileB0(b1 + ASZH * 4, (const uint32_t*)Bgv, ldb, 1, tid);
        else            cp_tileB1(b1 + ASZH * 4, (const __half*)Bgv, ldb, 1, tid);
        CPCOMMIT();
    }
    for (int kt = 0; kt < nkt; kt++) {
        if (kt + 2 < nkt) {
            int ns = (kt + 2) % 3;
            uint32_t bs = sb + (uint32_t)(ns * STGT) * 4;
            cp_tileA(bs, Ag, lda, kt + 2, tid);
            if (BMODE == 0) cp_tileB0(bs + ASZH * 4, (const uint32_t*)Bgv, ldb, kt + 2, tid);
            else            cp_tileB1(bs + ASZH * 4, (const __half*)Bgv, ldb, kt + 2, tid);
            CPCOMMIT();
        }
        int ahead = nkt - 1 - kt;
        if (ahead >= 2)      CPWAIT(2);
        else if (ahead == 1) CPWAIT(1);
        else                 CPWAIT(0);
        __syncthreads();
        int cs = kt % 3;
        compute_h<BMODE>(sm + cs * STGT, sm + cs * STGT + ASZH, acc, lane, wm, wn);
        if (kt + 1 < nkt) __syncthreads();
    }
}

// fp16 row-major epilogue (half2 stores)
__device__ __forceinline__ void store_acc_h(__half* C, int ldc,
                                            const float (&acc)[4][4][4],
                                            int lane, int wm, int wn) {
    int g = lane >> 2, t = lane & 3;
#pragma unroll
    for (int i = 0; i < 4; i++)
#pragma unroll
        for (int j = 0; j < 4; j++) {
            int r0 = (wm * 4 + i) * 16 + g;
            int c0 = (wn * 4 + j) * 8 + t * 2;
            __half2* p0 = (__half2*)(C + (size_t)r0 * ldc + c0);
            __half2* p1 = (__half2*)(C + (size_t)(r0 + 8) * ldc + c0);
            p0[0] = __floats2half2_rn(acc[i][j][0], acc[i][j][1]);
            p1[0] = __floats2half2_rn(acc[i][j][2], acc[i][j][3]);
        }
}

// ---------------------------------------------------------------------------
// Conversion kernels
// ---------------------------------------------------------------------------
__global__ __launch_bounds__(256) void k_cvtD(const float* __restrict__ data) {
    size_t i = (size_t)blockIdx.x * 256 + threadIdx.x;   // one float4 each
    const float4 v = ((const float4*)data)[i];
    __half2 h01 = __floats2half2_rn(v.x, v.y);
    __half2 h23 = __floats2half2_rn(v.z, v.w);
    ((uint2*)hD)[i] = make_uint2(*(uint32_t*)&h01, *(uint32_t*)&h23);
}

__global__ __launch_bounds__(256) void k_cvtW(const float* __restrict__ Wq,
                                              const float* __restrict__ Wk,
                                              const float* __restrict__ Wv) {
    size_t idx = (size_t)blockIdx.x * 256 + threadIdx.x;
    int slab = (int)(idx >> 20);          // 2048*512 per (which,h)
    int rem = (int)(idx & 1048575);
    int kp = rem >> 9, n = rem & 511;
    int which = slab >> 3, h = slab & 7;
    const float* W = (which == 0) ? Wq : (which == 1) ? Wk : Wv;
    const float* base = W + (size_t)h * E_ * HD_;
    float w0 = base[(size_t)(2 * kp) * HD_ + n];
    float w1 = base[(size_t)(2 * kp + 1) * HD_ + n];
    __half2 hh = __floats2half2_rn(w0, w1);
    hW2[idx] = *(uint32_t*)&hh;
}

__global__ __launch_bounds__(256) void k_cvtWo(const float* __restrict__ Wo) {
    size_t idx = (size_t)blockIdx.x * 256 + threadIdx.x;
    int kp = (int)(idx >> 12), n = (int)(idx & 4095);
    float w0 = Wo[(size_t)(2 * kp) * E_ + n];
    float w1 = Wo[(size_t)(2 * kp + 1) * E_ + n];
    __half2 hh = __floats2half2_rn(w0, w1);
    hWo2[idx] = *(uint32_t*)&hh;
}

// ---------------------------------------------------------------------------
// Kernel 1: fused QKV projection (fp16 core), group-major grid (L2 panels)
// ---------------------------------------------------------------------------
__global__ __launch_bounds__(256, 2) void k_qkv() {
    extern __shared__ __align__(16) uint32_t smu[];
    uint32_t sb = smem_u32(smu);
    int tid = threadIdx.x, lane = tid & 31, wid = tid >> 5;
    int wm = wid >> 2, wn = wid & 3;

    int gid = blockIdx.x;
    int grp = gid / (GN * QKV_MT);
    int rem = gid % (GN * QKV_MT);
    int m0 = (rem / GN) * BM;
    int n0 = (grp * GN + (rem % GN)) * BN;

    int which = n0 >> 12;
    int nr = n0 & 4095;
    int h = nr >> 9, d0 = nr & 511;
    const uint32_t* B2 = hW2 + (size_t)(which * 8 + h) * (2048u * 512u) + d0;
    const __half* Ag = hD + (size_t)m0 * E_;

    float acc[4][4][4];
    zero_acc(acc);
    gemm_h<0>(Ag, E_, B2, HD_, E_ / BK, smu, sb, acc, tid, lane, wm, wn);

    int b = m0 >> 9, t0 = m0 & 511;
    int bh = b * H_ + h;
    if (which <= 1) {
        __half* ob = which ? gKh : gQh;
        __half* C = ob + ((size_t)bh * T_ + t0) * HD_ + d0;
        store_acc_h(C, HD_, acc, lane, wm, wn);
    } else {
        // V: interleaved [bh][t/2][d][t&1]
        __half* vb = gVh + (size_t)bh * T_ * HD_;
        int g = lane >> 2, t = lane & 3;
#pragma unroll
        for (int i = 0; i < 4; i++)
#pragma unroll
            for (int j = 0; j < 4; j++) {
                int r0 = t0 + (wm * 4 + i) * 16 + g;
                int c0 = d0 + (wn * 4 + j) * 8 + t * 2;
#pragma unroll
                for (int rr = 0; rr < 2; rr++) {
                    int r = r0 + rr * 8;
                    size_t base = (((size_t)(r >> 1) * HD_) << 1) + (r & 1);
                    vb[base + (size_t)c0 * 2]       = __float2half(acc[i][j][rr * 2]);
                    vb[base + (size_t)(c0 + 1) * 2] = __float2half(acc[i][j][rr * 2 + 1]);
                }
            }
    }
}

// ---------------------------------------------------------------------------
// Kernel 2: scores S = Q K^T / sqrt(E), causal (fp16 core, B = K n-rows)
// ---------------------------------------------------------------------------
__global__ __launch_bounds__(256, 2) void k_scores() {
    int n0 = blockIdx.x * BN;
    int m0 = blockIdx.y * BM;
    if (n0 > m0) return;
    int z = blockIdx.z;

    extern __shared__ __align__(16) uint32_t smu[];
    uint32_t sb = smem_u32(smu);
    int tid = threadIdx.x, lane = tid & 31, wid = tid >> 5;
    int wm = wid >> 2, wn = wid & 3;

    const __half* Ag = gQh + (size_t)z * T_ * HD_ + (size_t)m0 * HD_;
    const __half* Bg = gKh + (size_t)z * T_ * HD_ + (size_t)n0 * HD_;

    float acc[4][4][4];
    zero_acc(acc);
    gemm_h<1>(Ag, HD_, Bg, HD_, HD_ / BK, smu, sb, acc, tid, lane, wm, wn);

    const float sc = 0.015625f;                  // 1/sqrt(4096)
    float* C = gS + (size_t)z * T_ * T_ + (size_t)m0 * T_ + n0;
    int g = lane >> 2, t = lane & 3;
#pragma unroll
    for (int i = 0; i < 4; i++)
#pragma unroll
        for (int j = 0; j < 4; j++) {
            int r0 = (wm * 4 + i) * 16 + g;
            int c0 = (wn * 4 + j) * 8 + t * 2;
            int gr = m0 + r0, gc = n0 + c0;
            float* p = C + (size_t)r0 * T_ + c0;
            if (gc     <= gr)     p[0]          = acc[i][j][0] * sc;
            if (gc + 1 <= gr)     p[1]          = acc[i][j][1] * sc;
            if (gc     <= gr + 8) p[8 * T_]     = acc[i][j][2] * sc;
            if (gc + 1 <= gr + 8) p[8 * T_ + 1] = acc[i][j][3] * sc;
        }
}

// ---------------------------------------------------------------------------
// Kernel 3: causal row softmax; fp32 in, fp16 probs out (tail zero-filled)
// ---------------------------------------------------------------------------
__global__ __launch_bounds__(128) void k_softmax() {
    int r = blockIdx.x;
    int z = blockIdx.y;
    const float* row = gS + (size_t)z * T_ * T_ + (size_t)r * T_;
    __half* prow = gPh + (size_t)z * T_ * T_ + (size_t)r * T_;
    int n = r + 1;
    int tid = threadIdx.x;
    __shared__ float sm[4];

    float v = -3.4e38f;
    for (int i = tid; i < n; i += 128) v = fmaxf(v, row[i]);
#pragma unroll
    for (int o = 16; o; o >>= 1) v = fmaxf(v, __shfl_xor_sync(0xffffffffu, v, o));
    if ((tid & 31) == 0) sm[tid >> 5] = v;
    __syncthreads();
    float M = fmaxf(fmaxf(sm[0], sm[1]), fmaxf(sm[2], sm[3]));
    __syncthreads();

    float s = 0.f;
    for (int i = tid; i < n; i += 128) s += __expf(row[i] - M);
#pragma unroll
    for (int o = 16; o; o >>= 1) s += __shfl_xor_sync(0xffffffffu, s, o);
    if ((tid & 31) == 0) sm[tid >> 5] = s;
    __syncthreads();
    float inv = 1.f / (sm[0] + sm[1] + sm[2] + sm[3]);

    for (int i = tid; i < T_; i += 128)
        prow[i] = (i < n) ? __float2half(__expf(row[i] - M) * inv) : __float2half(0.f);
}

// ---------------------------------------------------------------------------
// Kernel 4: O = P V (fp16 core, B = interleaved V; causal-truncated K loop)
// ---------------------------------------------------------------------------
__global__ __launch_bounds__(256, 2) void k_av() {
    extern __shared__ __align__(16) uint32_t smu[];
    uint32_t sb = smem_u32(smu);
    int tid = threadIdx.x, lane = tid & 31, wid = tid >> 5;
    int wm = wid >> 2, wn = wid & 3;

    int n0 = blockIdx.x * BN;      // d0
    int m0 = blockIdx.y * BM;      // t0
    int z = blockIdx.z;
    int b = z >> 3, h = z & 7;

    const __half* Ag = gPh + (size_t)z * T_ * T_ + (size_t)m0 * T_;
    const uint32_t* B2 = (const uint32_t*)gVh + (size_t)z * (T_ / 2) * HD_ + n0;
    int nkt = (m0 + BM) / BK;

    float acc[4][4][4];
    zero_acc(acc);
    gemm_h<0>(Ag, T_, B2, HD_, nkt, smu, sb, acc, tid, lane, wm, wn);

    __half* C = gYh + ((size_t)(b * T_ + m0)) * E_ + h * HD_ + n0;
    store_acc_h(C, E_, acc, lane, wm, wn);
}

// ---------------------------------------------------------------------------
// Kernel 5: out = Y @ Wo + bo (fp16 core, interleaved Wo; fp32 out)
// ---------------------------------------------------------------------------
__global__ __launch_bounds__(256, 2) void k_out(const float* __restrict__ bo,
                                                float* __restrict__ out) {
    extern __shared__ __align__(16) uint32_t smu[];
    uint32_t sb = smem_u32(smu);
    int tid = threadIdx.x, lane = tid & 31, wid = tid >> 5;
    int wm = wid >> 2, wn = wid & 3;

    int n0 = blockIdx.x * BN;
    int m0 = blockIdx.y * BM;

    const __half* Ag = gYh + (size_t)m0 * E_;
    const uint32_t* B2 = hWo2 + n0;

    float acc[4][4][4];
    zero_acc(acc);
    gemm_h<0>(Ag, E_, B2, E_, E_ / BK, smu, sb, acc, tid, lane, wm, wn);

    float* C = out + (size_t)m0 * E_ + n0;
    int g = lane >> 2, t = lane & 3;
#pragma unroll
    for (int i = 0; i < 4; i++)
#pragma unroll
        for (int j = 0; j < 4; j++) {
            int r0 = (wm * 4 + i) * 16 + g;
            int c0 = (wn * 4 + j) * 8 + t * 2;
            float b0 = bo[n0 + c0], b1 = bo[n0 + c0 + 1];
            float* p = C + (size_t)r0 * E_ + c0;
            p[0]           = acc[i][j][0] + b0;
            p[1]           = acc[i][j][1] + b1;
            p[8 * E_]      = acc[i][j][2] + b0;
            p[8 * E_ + 1]  = acc[i][j][3] + b1;
        }
}

// ---------------------------------------------------------------------------
extern "C" void kernel_launch(void* const* d_in, const int* in_sizes, int n_in,
                              void* d_out, int out_size) {
    const float* data = (const float*)d_in[0];
    const float* Wq   = (const float*)d_in[1];
    const float* Wk   = (const float*)d_in[2];
    const float* Wv   = (const float*)d_in[3];
    const float* Wo   = (const float*)d_in[4];
    const float* bo   = (const float*)d_in[5];
    float* out = (float*)d_out;

    static int attr_done = 0;
    if (!attr_done) {
        cudaFuncSetAttribute(k_qkv,    cudaFuncAttributeMaxDynamicSharedMemorySize, SMEM_I);
        cudaFuncSetAttribute(k_av,     cudaFuncAttributeMaxDynamicSharedMemorySize, SMEM_I);
        cudaFuncSetAttribute(k_out,    cudaFuncAttributeMaxDynamicSharedMemorySize, SMEM_I);
        cudaFuncSetAttribute(k_scores, cudaFuncAttributeMaxDynamicSharedMemorySize, SMEM_S);
        attr_done = 1;
    }

    k_cvtD <<<QSZ / 4 / 256, 256>>>(data);
    k_cvtW <<<3 * 8 * 2048 * 512 / 256, 256>>>(Wq, Wk, Wv);
    k_cvtWo<<<2048 * 4096 / 256, 256>>>(Wo);

    k_qkv   <<<QKV_NT * QKV_MT, 256, SMEM_I>>>();
    k_scores<<<dim3(4, 4, NBH), 256, SMEM_S>>>();
    k_softmax<<<dim3(T_, NBH),  128>>>();
    k_av    <<<dim3(4, 4, NBH), 256, SMEM_I>>>();
    k_out   <<<dim3(32, 64),    256, SMEM_I>>>(bo, out);
}

// round 15
// speedup vs baseline: 2.6589x; 1.1085x over previous
#include <cuda_runtime.h>
#include <cuda_fp16.h>
#include <cstdint>

// Problem dims
#define B_  16
#define T_  512
#define E_  4096
#define H_  8
#define HD_ 512
#define NBH 128            // B_*H_
#define QSZ 33554432       // B_*T_*E_

// fp16 GEMM tiling: CTA 128x128, BK=64 halves (32 u32 k-pairs), warp 64x32
#define BM 128
#define BN 128
#define BK 64
#define ASTH 36            // A smem row stride (u32): ldmatrix rows hit banks 4r..4r+3
#define BSTH 136           // interleaved-B stride (u32): frag bank 8t+g bijective
#define KSTH 36            // scores-B (n-row) stride (u32)
#define ASZH (BM * ASTH)   // 4608 u32
#define BSZH (32 * BSTH)   // 4352 u32
#define KSZH (BM * KSTH)   // 4608 u32
#define SMEM_I (3 * (ASZH + BSZH) * 4)   // 107520 B
#define SMEM_S (3 * (ASZH + KSZH) * 4)   // 110592 B

// k_qkv L2 grouping (proven): 16 n-tiles/group
#define GN 16
#define QKV_NT 96
#define QKV_MT 64

// ---------------------------------------------------------------------------
// Scratch (device globals)
// ---------------------------------------------------------------------------
__device__ __align__(128) __half   hD[QSZ];                    // data fp16 [8192][4096]
__device__ __align__(128) uint32_t hW2[3u * 8u * 2048u * 512u];// Wq|Wk|Wv k-pair interleaved
__device__ __align__(128) uint32_t hWo2[2048u * 4096u];        // Wo interleaved
__device__ __align__(128) __half   gQh[QSZ];                   // Q fp16 [bh][t][d]
__device__ __align__(128) __half   gKh[QSZ];                   // K fp16 [bh][s][d]
__device__ __align__(128) __half   gVh[QSZ];                   // V fp16 interleaved [bh][s/2][d][2]
__device__ float  gS[QSZ];                                     // scores fp32 [bh][t][s]
__device__ __align__(128) __half   gPh[QSZ];                   // probs fp16 [bh][t][s]
__device__ __align__(128) __half   gYh[QSZ];                   // attn out fp16 [b*T+t][E]

// ---------------------------------------------------------------------------
__device__ __forceinline__ uint32_t smem_u32(const void* p) {
    uint32_t a;
    asm("{ .reg .u64 t; cvta.to.shared.u64 t, %1; cvt.u32.u64 %0, t; }" : "=r"(a) : "l"(p));
    return a;
}
__device__ __forceinline__ void cpa16(uint32_t s, const void* g) {
    asm volatile("cp.async.cg.shared.global [%0], [%1], 16;" :: "r"(s), "l"(g));
}
#define CPCOMMIT() asm volatile("cp.async.commit_group;" ::: "memory")
#define CPWAIT(n)  asm volatile("cp.async.wait_group %0;" :: "n"(n) : "memory")

__device__ __forceinline__ void mma16(float* c, const uint32_t* a, const uint32_t* b) {
    asm volatile(
        "mma.sync.aligned.m16n8k16.row.col.f32.f16.f16.f32 "
        "{%0,%1,%2,%3},{%4,%5,%6,%7},{%8,%9},{%0,%1,%2,%3};\n"
        : "+f"(c[0]), "+f"(c[1]), "+f"(c[2]), "+f"(c[3])
        : "r"(a[0]), "r"(a[1]), "r"(a[2]), "r"(a[3]), "r"(b[0]), "r"(b[1]));
}

__device__ __forceinline__ void ldsm4(uint32_t* r, uint32_t addr) {
    asm volatile("ldmatrix.sync.aligned.m8n8.x4.shared.b16 {%0,%1,%2,%3}, [%4];"
                 : "=r"(r[0]), "=r"(r[1]), "=r"(r[2]), "=r"(r[3]) : "r"(addr));
}

__device__ __forceinline__ void zero_acc(float (&acc)[4][4][4]) {
#pragma unroll
    for (int i = 0; i < 4; i++)
#pragma unroll
        for (int j = 0; j < 4; j++)
#pragma unroll
            for (int k = 0; k < 4; k++) acc[i][j][k] = 0.f;
}

// ===========================================================================
// fp16 cp.async GEMM core, 3-stage, BK=64
// A: fp16 row-major [row][k]; B mode0: u32 interleaved [kp][n]; mode1: fp16 [n][k]
// A fragments via ldmatrix.x4 (conflict-free under stride 36).
// ===========================================================================
__device__ __forceinline__ void cp_tileA(uint32_t Aa, const __half* __restrict__ Ah,
                                         int lda, int kt, int tid) {
#pragma unroll
    for (int t = 0; t < 4; t++) {
        int idx = t * 256 + tid;
        int r = idx >> 3, kq = idx & 7;          // 128 rows x 8 float4
        cpa16(Aa + (uint32_t)(r * ASTH + kq * 4) * 4,
              Ah + (size_t)r * lda + kt * 64 + kq * 8);
    }
}
__device__ __forceinline__ void cp_tileB0(uint32_t Ba, const uint32_t* __restrict__ B2,
                                          int ldb2, int kt, int tid) {
#pragma unroll
    for (int t = 0; t < 4; t++) {
        int idx = t * 256 + tid;
        int kp = idx >> 5, nq = idx & 31;        // 32 kp-rows x 32 float4
        cpa16(Ba + (uint32_t)(kp * BSTH + nq * 4) * 4,
              B2 + (size_t)(kt * 32 + kp) * ldb2 + nq * 4);
    }
}
__device__ __forceinline__ void cp_tileB1(uint32_t Ba, const __half* __restrict__ Bh,
                                          int ldb, int kt, int tid) {
#pragma unroll
    for (int t = 0; t < 4; t++) {
        int idx = t * 256 + tid;
        int r = idx >> 3, kq = idx & 7;          // 128 n-rows x 8 float4
        cpa16(Ba + (uint32_t)(r * KSTH + kq * 4) * 4,
              Bh + (size_t)r * ldb + kt * 64 + kq * 8);
    }
}

// aoff[i]: per-lane u32 offset of this lane's ldmatrix row for a-frag i (s=0)
__device__ __forceinline__ void mk_aoff(uint32_t (&aoff)[4], int lane, int wm) {
    int rr = (lane & 7) + ((lane >> 3) & 1) * 8;
    int cc = (lane >> 4) & 1;
#pragma unroll
    for (int i = 0; i < 4; i++)
        aoff[i] = (uint32_t)(((wm * 4 + i) * 16 + rr) * ASTH + cc * 4);
}

template <int BMODE>
__device__ __forceinline__ void compute_h(uint32_t sAb, const uint32_t* Bs,
                                          float (&acc)[4][4][4],
                                          const uint32_t (&aoff)[4],
                                          int lane, int wn) {
    int g = lane >> 2, t = lane & 3;
#pragma unroll
    for (int s = 0; s < 4; s++) {                // four k16 steps per BK=64
        uint32_t a[4][4];
        uint32_t b[4][2];
#pragma unroll
        for (int i = 0; i < 4; i++)
            ldsm4(a[i], sAb + (aoff[i] + s * 8) * 4);
#pragma unroll
        for (int j = 0; j < 4; j++) {
            if (BMODE == 0) {
                const uint32_t* bp = Bs + (s * 8 + t) * BSTH + (wn * 4 + j) * 8 + g;
                b[j][0] = bp[0];
                b[j][1] = bp[4 * BSTH];
            } else {
                const uint32_t* bp = Bs + ((wn * 4 + j) * 8 + g) * KSTH + s * 8 + t;
                b[j][0] = bp[0];
                b[j][1] = bp[4];
            }
        }
#pragma unroll
        for (int i = 0; i < 4; i++)
#pragma unroll
            for (int j = 0; j < 4; j++)
                mma16(acc[i][j], a[i], b[j]);
    }
}

// 3-stage driver; hazard discipline identical to the proven R9/R14 loop.
template <int BMODE>
__device__ __forceinline__ void gemm_h(const __half* __restrict__ Ag, int lda,
                                       const void* __restrict__ Bgv, int ldb,
                                       int nkt, const uint32_t* sm, uint32_t sb,
                                       float (&acc)[4][4][4],
                                       const uint32_t (&aoff)[4],
                                       int tid, int lane, int wn) {
    const int BSZT = (BMODE ? KSZH : BSZH);
    const int STGT = ASZH + BSZT;

    cp_tileA(sb, Ag, lda, 0, tid);
    if (BMODE == 0) cp_tileB0(sb + ASZH * 4, (const uint32_t*)Bgv, ldb, 0, tid);
    else            cp_tileB1(sb + ASZH * 4, (const __half*)Bgv, ldb, 0, tid);
    CPCOMMIT();
    if (nkt > 1) {
        uint32_t b1 = sb + (uint32_t)STGT * 4;
        cp_tileA(b1, Ag, lda, 1, tid);
        if (BMODE == 0) cp_tileB0(b1 + ASZH * 4, (const uint32_t*)Bgv, ldb, 1, tid);
        else            cp_tileB1(b1 + ASZH * 4, (const __half*)Bgv, ldb, 1, tid);
        CPCOMMIT();
    }
    for (int kt = 0; kt < nkt; kt++) {
        if (kt + 2 < nkt) {
            int ns = (kt + 2) % 3;
            uint32_t bs = sb + (uint32_t)(ns * STGT) * 4;
            cp_tileA(bs, Ag, lda, kt + 2, tid);
            if (BMODE == 0) cp_tileB0(bs + ASZH * 4, (const uint32_t*)Bgv, ldb, kt + 2, tid);
            else            cp_tileB1(bs + ASZH * 4, (const __half*)Bgv, ldb, kt + 2, tid);
            CPCOMMIT();
        }
        int ahead = nkt - 1 - kt;
        if (ahead >= 2)      CPWAIT(2);
        else if (ahead == 1) CPWAIT(1);
        else                 CPWAIT(0);
        __syncthreads();
        int cs = kt % 3;
        compute_h<BMODE>(sb + (uint32_t)(cs * STGT) * 4,
                         sm + cs * STGT + ASZH, acc, aoff, lane, wn);
        if (kt + 1 < nkt) __syncthreads();
    }
}

// fp16 row-major epilogue (half2 stores)
__device__ __forceinline__ void store_acc_h(__half* C, int ldc,
                                            const float (&acc)[4][4][4],
                                            int lane, int wm, int wn) {
    int g = lane >> 2, t = lane & 3;
#pragma unroll
    for (int i = 0; i < 4; i++)
#pragma unroll
        for (int j = 0; j < 4; j++) {
            int r0 = (wm * 4 + i) * 16 + g;
            int c0 = (wn * 4 + j) * 8 + t * 2;
            __half2* p0 = (__half2*)(C + (size_t)r0 * ldc + c0);
            __half2* p1 = (__half2*)(C + (size_t)(r0 + 8) * ldc + c0);
            p0[0] = __floats2half2_rn(acc[i][j][0], acc[i][j][1]);
            p1[0] = __floats2half2_rn(acc[i][j][2], acc[i][j][3]);
        }
}

// ---------------------------------------------------------------------------
// Conversion kernels
// ---------------------------------------------------------------------------
__global__ __launch_bounds__(256) void k_cvtD(const float* __restrict__ data) {
    size_t i = (size_t)blockIdx.x * 256 + threadIdx.x;   // one float4 each
    const float4 v = ((const float4*)data)[i];
    __half2 h01 = __floats2half2_rn(v.x, v.y);
    __half2 h23 = __floats2half2_rn(v.z, v.w);
    ((uint2*)hD)[i] = make_uint2(*(uint32_t*)&h01, *(uint32_t*)&h23);
}

__global__ __launch_bounds__(256) void k_cvtW(const float* __restrict__ Wq,
                                              const float* __restrict__ Wk,
                                              const float* __restrict__ Wv) {
    size_t idx = (size_t)blockIdx.x * 256 + threadIdx.x;
    int slab = (int)(idx >> 20);          // 2048*512 per (which,h)
    int rem = (int)(idx & 1048575);
    int kp = rem >> 9, n = rem & 511;
    int which = slab >> 3, h = slab & 7;
    const float* W = (which == 0) ? Wq : (which == 1) ? Wk : Wv;
    const float* base = W + (size_t)h * E_ * HD_;
    float w0 = base[(size_t)(2 * kp) * HD_ + n];
    float w1 = base[(size_t)(2 * kp + 1) * HD_ + n];
    __half2 hh = __floats2half2_rn(w0, w1);
    hW2[idx] = *(uint32_t*)&hh;
}

__global__ __launch_bounds__(256) void k_cvtWo(const float* __restrict__ Wo) {
    size_t idx = (size_t)blockIdx.x * 256 + threadIdx.x;
    int kp = (int)(idx >> 12), n = (int)(idx & 4095);
    float w0 = Wo[(size_t)(2 * kp) * E_ + n];
    float w1 = Wo[(size_t)(2 * kp + 1) * E_ + n];
    __half2 hh = __floats2half2_rn(w0, w1);
    hWo2[idx] = *(uint32_t*)&hh;
}

// ---------------------------------------------------------------------------
// Kernel 1: fused QKV projection (fp16 core), group-major grid (L2 panels)
// ---------------------------------------------------------------------------
__global__ __launch_bounds__(256, 2) void k_qkv() {
    extern __shared__ __align__(16) uint32_t smu[];
    uint32_t sb = smem_u32(smu);
    int tid = threadIdx.x, lane = tid & 31, wid = tid >> 5;
    int wm = wid >> 2, wn = wid & 3;
    uint32_t aoff[4];
    mk_aoff(aoff, lane, wm);

    int gid = blockIdx.x;
    int grp = gid / (GN * QKV_MT);
    int rem = gid % (GN * QKV_MT);
    int m0 = (rem / GN) * BM;
    int n0 = (grp * GN + (rem % GN)) * BN;

    int which = n0 >> 12;
    int nr = n0 & 4095;
    int h = nr >> 9, d0 = nr & 511;
    const uint32_t* B2 = hW2 + (size_t)(which * 8 + h) * (2048u * 512u) + d0;
    const __half* Ag = hD + (size_t)m0 * E_;

    float acc[4][4][4];
    zero_acc(acc);
    gemm_h<0>(Ag, E_, B2, HD_, E_ / BK, smu, sb, acc, aoff, tid, lane, wn);

    int b = m0 >> 9, t0 = m0 & 511;
    int bh = b * H_ + h;
    if (which <= 1) {
        __half* ob = which ? gKh : gQh;
        __half* C = ob + ((size_t)bh * T_ + t0) * HD_ + d0;
        store_acc_h(C, HD_, acc, lane, wm, wn);
    } else {
        // V: interleaved [bh][t/2][d][t&1]
        __half* vb = gVh + (size_t)bh * T_ * HD_;
        int g = lane >> 2, t = lane & 3;
#pragma unroll
        for (int i = 0; i < 4; i++)
#pragma unroll
            for (int j = 0; j < 4; j++) {
                int r0 = t0 + (wm * 4 + i) * 16 + g;
                int c0 = d0 + (wn * 4 + j) * 8 + t * 2;
#pragma unroll
                for (int rr = 0; rr < 2; rr++) {
                    int r = r0 + rr * 8;
                    size_t base = (((size_t)(r >> 1) * HD_) << 1) + (r & 1);
                    vb[base + (size_t)c0 * 2]       = __float2half(acc[i][j][rr * 2]);
                    vb[base + (size_t)(c0 + 1) * 2] = __float2half(acc[i][j][rr * 2 + 1]);
                }
            }
    }
}

// ---------------------------------------------------------------------------
// Kernel 2: scores S = Q K^T / sqrt(E), causal (fp16 core, B = K n-rows)
// ---------------------------------------------------------------------------
__global__ __launch_bounds__(256, 2) void k_scores() {
    int n0 = blockIdx.x * BN;
    int m0 = blockIdx.y * BM;
    if (n0 > m0) return;
    int z = blockIdx.z;

    extern __shared__ __align__(16) uint32_t smu[];
    uint32_t sb = smem_u32(smu);
    int tid = threadIdx.x, lane = tid & 31, wid = tid >> 5;
    int wm = wid >> 2, wn = wid & 3;
    uint32_t aoff[4];
    mk_aoff(aoff, lane, wm);

    const __half* Ag = gQh + (size_t)z * T_ * HD_ + (size_t)m0 * HD_;
    const __half* Bg = gKh + (size_t)z * T_ * HD_ + (size_t)n0 * HD_;

    float acc[4][4][4];
    zero_acc(acc);
    gemm_h<1>(Ag, HD_, Bg, HD_, HD_ / BK, smu, sb, acc, aoff, tid, lane, wn);

    const float sc = 0.015625f;                  // 1/sqrt(4096)
    float* C = gS + (size_t)z * T_ * T_ + (size_t)m0 * T_ + n0;
    int g = lane >> 2, t = lane & 3;
#pragma unroll
    for (int i = 0; i < 4; i++)
#pragma unroll
        for (int j = 0; j < 4; j++) {
            int r0 = (wm * 4 + i) * 16 + g;
            int c0 = (wn * 4 + j) * 8 + t * 2;
            int gr = m0 + r0, gc = n0 + c0;
            float* p = C + (size_t)r0 * T_ + c0;
            if (gc     <= gr)     p[0]          = acc[i][j][0] * sc;
            if (gc + 1 <= gr)     p[1]          = acc[i][j][1] * sc;
            if (gc     <= gr + 8) p[8 * T_]     = acc[i][j][2] * sc;
            if (gc + 1 <= gr + 8) p[8 * T_ + 1] = acc[i][j][3] * sc;
        }
}

// ---------------------------------------------------------------------------
// Kernel 3: causal row softmax; fp32 in, fp16 probs out (tail zero-filled)
// ---------------------------------------------------------------------------
__global__ __launch_bounds__(128) void k_softmax() {
    int r = blockIdx.x;
    int z = blockIdx.y;
    const float* row = gS + (size_t)z * T_ * T_ + (size_t)r * T_;
    __half* prow = gPh + (size_t)z * T_ * T_ + (size_t)r * T_;
    int n = r + 1;
    int tid = threadIdx.x;
    __shared__ float sm[4];

    float v = -3.4e38f;
    for (int i = tid; i < n; i += 128) v = fmaxf(v, row[i]);
#pragma unroll
    for (int o = 16; o; o >>= 1) v = fmaxf(v, __shfl_xor_sync(0xffffffffu, v, o));
    if ((tid & 31) == 0) sm[tid >> 5] = v;
    __syncthreads();
    float M = fmaxf(fmaxf(sm[0], sm[1]), fmaxf(sm[2], sm[3]));
    __syncthreads();

    float s = 0.f;
    for (int i = tid; i < n; i += 128) s += __expf(row[i] - M);
#pragma unroll
    for (int o = 16; o; o >>= 1) s += __shfl_xor_sync(0xffffffffu, s, o);
    if ((tid & 31) == 0) sm[tid >> 5] = s;
    __syncthreads();
    float inv = 1.f / (sm[0] + sm[1] + sm[2] + sm[3]);

    for (int i = tid; i < T_; i += 128)
        prow[i] = (i < n) ? __float2half(__expf(row[i] - M) * inv) : __float2half(0.f);
}

// ---------------------------------------------------------------------------
// Kernel 4: O = P V (fp16 core, B = interleaved V; causal-truncated K loop)
// ---------------------------------------------------------------------------
__global__ __launch_bounds__(256, 2) void k_av() {
    extern __shared__ __align__(16) uint32_t smu[];
    uint32_t sb = smem_u32(smu);
    int tid = threadIdx.x, lane = tid & 31, wid = tid >> 5;
    int wm = wid >> 2, wn = wid & 3;
    uint32_t aoff[4];
    mk_aoff(aoff, lane, wm);

    int n0 = blockIdx.x * BN;      // d0
    int m0 = blockIdx.y * BM;      // t0
    int z = blockIdx.z;
    int b = z >> 3, h = z & 7;

    const __half* Ag = gPh + (size_t)z * T_ * T_ + (size_t)m0 * T_;
    const uint32_t* B2 = (const uint32_t*)gVh + (size_t)z * (T_ / 2) * HD_ + n0;
    int nkt = (m0 + BM) / BK;

    float acc[4][4][4];
    zero_acc(acc);
    gemm_h<0>(Ag, T_, B2, HD_, nkt, smu, sb, acc, aoff, tid, lane, wn);

    __half* C = gYh + ((size_t)(b * T_ + m0)) * E_ + h * HD_ + n0;
    store_acc_h(C, E_, acc, lane, wm, wn);
}

// ---------------------------------------------------------------------------
// Kernel 5: out = Y @ Wo + bo (fp16 core, interleaved Wo; fp32 out)
// ---------------------------------------------------------------------------
__global__ __launch_bounds__(256, 2) void k_out(const float* __restrict__ bo,
                                                float* __restrict__ out) {
    extern __shared__ __align__(16) uint32_t smu[];
    uint32_t sb = smem_u32(smu);
    int tid = threadIdx.x, lane = tid & 31, wid = tid >> 5;
    int wm = wid >> 2, wn = wid & 3;
    uint32_t aoff[4];
    mk_aoff(aoff, lane, wm);

    int n0 = blockIdx.x * BN;
    int m0 = blockIdx.y * BM;

    const __half* Ag = gYh + (size_t)m0 * E_;
    const uint32_t* B2 = hWo2 + n0;

    float acc[4][4][4];
    zero_acc(acc);
    gemm_h<0>(Ag, E_, B2, E_, E_ / BK, smu, sb, acc, aoff, tid, lane, wn);

    float* C = out + (size_t)m0 * E_ + n0;
    int g = lane >> 2, t = lane & 3;
#pragma unroll
    for (int i = 0; i < 4; i++)
#pragma unroll
        for (int j = 0; j < 4; j++) {
            int r0 = (wm * 4 + i) * 16 + g;
            int c0 = (wn * 4 + j) * 8 + t * 2;
            float b0 = bo[n0 + c0], b1 = bo[n0 + c0 + 1];
            float* p = C + (size_t)r0 * E_ + c0;
            p[0]           = acc[i][j][0] + b0;
            p[1]           = acc[i][j][1] + b1;
            p[8 * E_]      = acc[i][j][2] + b0;
            p[8 * E_ + 1]  = acc[i][j][3] + b1;
        }
}

// ---------------------------------------------------------------------------
extern "C" void kernel_launch(void* const* d_in, const int* in_sizes, int n_in,
                              void* d_out, int out_size) {
    const float* data = (const float*)d_in[0];
    const float* Wq   = (const float*)d_in[1];
    const float* Wk   = (const float*)d_in[2];
    const float* Wv   = (const float*)d_in[3];
    const float* Wo   = (const float*)d_in[4];
    const float* bo   = (const float*)d_in[5];
    float* out = (float*)d_out;

    static int attr_done = 0;
    if (!attr_done) {
        cudaFuncSetAttribute(k_qkv,    cudaFuncAttributeMaxDynamicSharedMemorySize, SMEM_I);
        cudaFuncSetAttribute(k_av,     cudaFuncAttributeMaxDynamicSharedMemorySize, SMEM_I);
        cudaFuncSetAttribute(k_out,    cudaFuncAttributeMaxDynamicSharedMemorySize, SMEM_I);
        cudaFuncSetAttribute(k_scores, cudaFuncAttributeMaxDynamicSharedMemorySize, SMEM_S);
        attr_done = 1;
    }

    k_cvtD <<<QSZ / 4 / 256, 256>>>(data);
    k_cvtW <<<3 * 8 * 2048 * 512 / 256, 256>>>(Wq, Wk, Wv);
    k_cvtWo<<<2048 * 4096 / 256, 256>>>(Wo);

    k_qkv   <<<QKV_NT * QKV_MT, 256, SMEM_I>>>();
    k_scores<<<dim3(4, 4, NBH), 256, SMEM_S>>>();
    k_softmax<<<dim3(T_, NBH),  128>>>();
    k_av    <<<dim3(4, 4, NBH), 256, SMEM_I>>>();
    k_out   <<<dim3(32, 64),    256, SMEM_I>>>(bo, out);
}